// round 3
// baseline (speedup 1.0000x reference)
#include <cuda_runtime.h>

// WavetableSynth: B=16, L=48000, W=64, LWT=512
// inputs: pitch (B*L f32), envelope (B*L f32), attention (B*L*W f32), wavetables (W*LWT f32)
// output: (B, L, 1) f32

#define BB 16
#define LL 48000
#define WW 64
#define LWT_ 512

static constexpr float K_INC = 512.0f / 16000.0f; // 0.032f in f32

#define NT1 3000   // 48000 / 16
#define NT2 188    // ceil(3000 / 16)
#define NT3 12     // ceil(188 / 16)

// cumsum scratch (no device allocations allowed)
__device__ float g_cum[BB * LL];

// ---------------------------------------------------------------------------
// Kernel 1: emulate XLA ReduceWindowRewriter cumsum (base_length = 16):
// radix-16 hierarchy, strictly sequential left-to-right adds within each
// 16-group at every level, one fadd of the exclusive group prefix per element
// (prefix omitted for group 0: XLA's 0+x is exact). Zero padding is exact.
// One CTA per batch row.
// ---------------------------------------------------------------------------
__global__ void __launch_bounds__(256, 1) scan16_kernel(const float* __restrict__ pitch) {
    __shared__ float G1[NT1], P2[NT1];
    __shared__ float G2[NT2], P3[NT2];
    __shared__ float G3[NT3], P4[NT3];

    const int b = blockIdx.x;
    const float* p = pitch + b * LL;
    const int t = threadIdx.x;
    const int T = blockDim.x;

    // ---- level-1 tile sums: G1[t] = seq sum of 16 leaves RN(K*p) ----
    for (int i = t; i < NT1; i += T) {
        const float* q = p + i * 16;
        float acc = __fmul_rn(K_INC, q[0]);
        #pragma unroll
        for (int j = 1; j < 16; j++) acc = __fadd_rn(acc, __fmul_rn(K_INC, q[j]));
        G1[i] = acc;
    }
    __syncthreads();

    // ---- level-2 group sums over G1 (last group has 8 real elems + zeros) ----
    for (int u = t; u < NT2; u += T) {
        int base = u * 16, end = min(base + 16, NT1);
        float acc = G1[base];
        for (int i = base + 1; i < end; i++) acc = __fadd_rn(acc, G1[i]);
        G2[u] = acc;
    }
    __syncthreads();

    // ---- level-3 group sums over G2 (last group has 12 real elems) ----
    if (t < NT3) {
        int base = t * 16, end = min(base + 16, NT2);
        float acc = G2[base];
        for (int i = base + 1; i < end; i++) acc = __fadd_rn(acc, G2[i]);
        G3[t] = acc;
    }
    __syncthreads();

    // ---- top scan over 12 values: native sequential inclusive ----
    if (t == 0) {
        float acc = G3[0];
        P4[0] = acc;
        for (int w = 1; w < NT3; w++) { acc = __fadd_rn(acc, G3[w]); P4[w] = acc; }
    }
    __syncthreads();

    // ---- P3[u]: inner seq scan of G2 within its 16-group + excl P4 prefix ----
    for (int u = t; u < NT2; u += T) {
        int w = u >> 4, base = w * 16;
        float acc = G2[base];
        for (int i = base + 1; i <= u; i++) acc = __fadd_rn(acc, G2[i]);
        P3[u] = (w > 0) ? __fadd_rn(P4[w - 1], acc) : acc;
    }
    __syncthreads();

    // ---- P2[t]: inner seq scan of G1 within its 16-group + excl P3 prefix ----
    for (int i = t; i < NT1; i += T) {
        int u = i >> 4, base = u * 16;
        float acc = G1[base];
        for (int k = base + 1; k <= i; k++) acc = __fadd_rn(acc, G1[k]);
        P2[i] = (u > 0) ? __fadd_rn(P3[u - 1], acc) : acc;
    }
    __syncthreads();

    // ---- emission: cum[16t+j] = inner seq scan of leaves + excl P2 prefix ----
    float* cum = g_cum + b * LL;
    for (int i = t; i < NT1; i += T) {
        const float* q = p + i * 16;
        float* o = cum + i * 16;
        if (i == 0) {
            float acc = __fmul_rn(K_INC, q[0]);
            o[0] = acc;
            #pragma unroll
            for (int j = 1; j < 16; j++) {
                acc = __fadd_rn(acc, __fmul_rn(K_INC, q[j]));
                o[j] = acc;
            }
        } else {
            float pref = P2[i - 1];
            float acc = __fmul_rn(K_INC, q[0]);
            o[0] = __fadd_rn(pref, acc);
            #pragma unroll
            for (int j = 1; j < 16; j++) {
                acc = __fadd_rn(acc, __fmul_rn(K_INC, q[j]));
                o[j] = __fadd_rn(pref, acc);
            }
        }
    }
}

// ---------------------------------------------------------------------------
// Kernel 2: one sample per thread. Wavetables transposed in smem [512][68].
// ---------------------------------------------------------------------------
#define WT_STRIDE 68
#define MAIN_SMEM (LWT_ * WT_STRIDE * 4)

__global__ void __launch_bounds__(1024, 1) synth_kernel(
    const float*  __restrict__ pitch,     // row 0 used for inc0
    const float*  __restrict__ env,
    const float4* __restrict__ att4,      // [B*L][16] float4
    const float*  __restrict__ wt,        // [64][512]
    float*        __restrict__ out)
{
    extern __shared__ float s_wt[]; // [512][WT_STRIDE]

    const int t    = threadIdx.x;
    const int lane = t & 31;
    const int wrp  = t >> 5;
    for (int w = wrp; w < WW; w += 32) {
        const float4* row = (const float4*)(wt + w * LWT_);
        for (int c4 = lane; c4 < LWT_ / 4; c4 += 32) {
            float4 v = row[c4];
            int idx = c4 * 4;
            s_wt[(idx + 0) * WT_STRIDE + w] = v.x;
            s_wt[(idx + 1) * WT_STRIDE + w] = v.y;
            s_wt[(idx + 2) * WT_STRIDE + w] = v.z;
            s_wt[(idx + 3) * WT_STRIDE + w] = v.w;
        }
    }
    __syncthreads();

    const int stride = gridDim.x * blockDim.x;
    for (int s = blockIdx.x * blockDim.x + t; s < BB * LL; s += stride) {
        const int l = s % LL;

        // index = cum - increment[0, l]  (XLA contracts sub(cum, mul) -> fma)
        float x = fmaf(-K_INC, pitch[l], g_cum[s]);
        float r = fmodf(x, 512.0f);
        if (r < 0.0f) r = __fadd_rn(r, 512.0f);
        if (__fsub_rn(512.0f, r) < 1e-5f) r = 0.0f;

        const float low   = floorf(r);
        const float alpha = __fsub_rn(r, low);
        const int il = (int)low;
        const int ih = ((int)ceilf(r)) & (LWT_ - 1);

        const float4* wlo = (const float4*)(s_wt + il * WT_STRIDE);
        const float4* whi = (const float4*)(s_wt + ih * WT_STRIDE);
        const float4* a   = att4 + (size_t)s * (WW / 4);

        float acc = 0.0f;
#pragma unroll
        for (int g = 0; g < WW / 4; g++) {
            float4 av = a[g];
            float4 lo = wlo[g];
            float4 hi = whi[g];
            acc = fmaf(av.x, fmaf(alpha, hi.x - lo.x, lo.x), acc);
            acc = fmaf(av.y, fmaf(alpha, hi.y - lo.y, lo.y), acc);
            acc = fmaf(av.z, fmaf(alpha, hi.z - lo.z, lo.z), acc);
            acc = fmaf(av.w, fmaf(alpha, hi.w - lo.w, lo.w), acc);
        }
        out[s] = acc * env[s];
    }
}

// ---------------------------------------------------------------------------
extern "C" void kernel_launch(void* const* d_in, const int* in_sizes, int n_in,
                              void* d_out, int out_size) {
    const float* pitch = (const float*)d_in[0];
    const float* env   = (const float*)d_in[1];
    const float* att   = (const float*)d_in[2];
    const float* wt    = (const float*)d_in[3];
    float* out         = (float*)d_out;

    cudaFuncSetAttribute(synth_kernel, cudaFuncAttributeMaxDynamicSharedMemorySize, MAIN_SMEM);

    scan16_kernel<<<BB, 256>>>(pitch);
    synth_kernel<<<148, 1024, MAIN_SMEM>>>(pitch, env, (const float4*)att, wt, out);
}

// round 5
// speedup vs baseline: 1.2470x; 1.2470x over previous
#include <cuda_runtime.h>

// WavetableSynth: B=16, L=48000, W=64, LWT=512
// inputs: pitch (B*L f32), envelope (B*L f32), attention (B*L*W f32), wavetables (W*LWT f32)
// output: (B, L, 1) f32

#define BB 16
#define LL 48000
#define WW 64
#define LWT_ 512

static constexpr float K_INC = 512.0f / 16000.0f; // 0.032f in f32

#define NT1 3000   // 48000 / 16
#define NT2 188    // ceil(3000 / 16)
#define NT3 12     // ceil(188 / 16)

// scratch (no device allocations allowed; referenced ONLY from device code)
__device__ float g_G1[BB * NT1];
__device__ float g_P3[BB * NT2];
__device__ float g_r [BB * LL];    // final wavetable index per sample, in [0, 512)

// ---------------------------------------------------------------------------
// K1: tile sums G1[b][i] = sequential sum of 16 leaves RN(K*pitch), exact
// op order of the XLA radix-16 scan. One thread per tile, 48000 tiles.
// ---------------------------------------------------------------------------
__global__ void __launch_bounds__(256) k1_tilesums(const float* __restrict__ pitch) {
    int tid = blockIdx.x * blockDim.x + threadIdx.x;
    if (tid >= BB * NT1) return;
    int b = tid / NT1, i = tid - b * NT1;
    const float4* q = (const float4*)(pitch + b * LL + i * 16);
    float4 v0 = q[0], v1 = q[1], v2 = q[2], v3 = q[3];
    float lv[16] = {v0.x,v0.y,v0.z,v0.w, v1.x,v1.y,v1.z,v1.w,
                    v2.x,v2.y,v2.z,v2.w, v3.x,v3.y,v3.z,v3.w};
    float acc = __fmul_rn(K_INC, lv[0]);
    #pragma unroll
    for (int j = 1; j < 16; j++) acc = __fadd_rn(acc, __fmul_rn(K_INC, lv[j]));
    g_G1[tid] = acc;
}

// ---------------------------------------------------------------------------
// K2: per batch row — G2 (level-2 sums), G3, P4 (top scan), P3 (level-2
// prefixes). Exact op order of round-3 scan. One CTA per row, tiny.
// ---------------------------------------------------------------------------
__global__ void __launch_bounds__(192) k2_midscan() {
    __shared__ float G2[NT2], P4[NT3];
    const int b = blockIdx.x;
    const int t = threadIdx.x;
    const float* G1 = g_G1 + b * NT1;

    if (t < NT2) {
        int base = t * 16, end = min(base + 16, NT1);
        float acc = G1[base];
        for (int i = base + 1; i < end; i++) acc = __fadd_rn(acc, G1[i]);
        G2[t] = acc;
    }
    __syncthreads();
    if (t == 0) {
        float G3[NT3];
        for (int w = 0; w < NT3; w++) {
            int base = w * 16, end = min(base + 16, NT2);
            float acc = G2[base];
            for (int i = base + 1; i < end; i++) acc = __fadd_rn(acc, G2[i]);
            G3[w] = acc;
        }
        float acc = G3[0];
        P4[0] = acc;
        for (int w = 1; w < NT3; w++) { acc = __fadd_rn(acc, G3[w]); P4[w] = acc; }
    }
    __syncthreads();
    if (t < NT2) {
        int w = t >> 4, base = w * 16;
        float acc = G2[base];
        for (int i = base + 1; i <= t; i++) acc = __fadd_rn(acc, G2[i]);
        g_P3[b * NT2 + t] = (w > 0) ? __fadd_rn(P4[w - 1], acc) : acc;
    }
}

// ---------------------------------------------------------------------------
// K3: emission. One thread per tile. Reconstructs P2[i-1] inline from G1+P3
// (same adds as round 3), runs the leaf scan, and directly produces the
// modded wavetable index r = clamp(mod(cum - K*pitch0, 512)).
// ---------------------------------------------------------------------------
__global__ void __launch_bounds__(256) k3_emit(const float* __restrict__ pitch) {
    int tid = blockIdx.x * blockDim.x + threadIdx.x;
    if (tid >= BB * NT1) return;
    int b = tid / NT1, i = tid - b * NT1;
    const float* p  = pitch + b * LL + i * 16;
    const float* p0 = pitch + i * 16;            // batch row 0 (increment[0])
    float* ro = g_r + b * LL + i * 16;

    // pref = P2[i-1]
    float pref = 0.0f;
    bool has_pref = (i > 0);
    if (has_pref) {
        int j = i - 1, u = j >> 4, base = u * 16;
        const float* G1 = g_G1 + b * NT1;
        float acc = G1[base];
        for (int k = base + 1; k <= j; k++) acc = __fadd_rn(acc, G1[k]);
        pref = (u > 0) ? __fadd_rn(g_P3[b * NT2 + (u - 1)], acc) : acc;
    }

    float acc = 0.0f;
    #pragma unroll
    for (int j = 0; j < 16; j++) {
        float leaf = __fmul_rn(K_INC, p[j]);
        acc = (j == 0) ? leaf : __fadd_rn(acc, leaf);
        float cum = has_pref ? __fadd_rn(pref, acc) : acc;
        // index = cum - increment[0]  (XLA contracts sub(cum, mul) -> fma)
        float x = fmaf(-K_INC, p0[j], cum);
        float r = fmodf(x, 512.0f);
        if (r < 0.0f) r = __fadd_rn(r, 512.0f);
        if (__fsub_rn(512.0f, r) < 1e-5f) r = 0.0f;
        ro[j] = r;
    }
}

// ---------------------------------------------------------------------------
// K4 synth: half-warp per sample. Lane ls in [0,16) owns wavetable entries
// w in [4ls, 4ls+4). Wavetables transposed in smem [512][68] (float4 rows);
// each LDS.128 phase reads 32 consecutive words of one row -> conflict-free
// for arbitrary row indices. Dot finished with 4 shfl_xor over 16 lanes.
// Reads g_r directly (device symbol — NOT passed from host).
// ---------------------------------------------------------------------------
#define WT_STRIDE 68
#define MAIN_SMEM (LWT_ * WT_STRIDE * 4)

__global__ void __launch_bounds__(1024, 1) synth_kernel(
    const float*  __restrict__ env,
    const float4* __restrict__ att4,      // [B*L][16] float4
    const float*  __restrict__ wt,        // [64][512]
    float*        __restrict__ out)
{
    extern __shared__ float s_wt[]; // [512][WT_STRIDE]

    const int t    = threadIdx.x;
    const int lane = t & 31;
    const int wrp  = t >> 5;          // 32 warps/CTA
    // transpose: warp per wavetable row, coalesced float4 reads
    for (int w = wrp; w < WW; w += 32) {
        const float4* row = (const float4*)(wt + w * LWT_);
        for (int c4 = lane; c4 < LWT_ / 4; c4 += 32) {
            float4 v = row[c4];
            int idx = c4 * 4;
            s_wt[(idx + 0) * WT_STRIDE + w] = v.x;
            s_wt[(idx + 1) * WT_STRIDE + w] = v.y;
            s_wt[(idx + 2) * WT_STRIDE + w] = v.z;
            s_wt[(idx + 3) * WT_STRIDE + w] = v.w;
        }
    }
    __syncthreads();

    const int half = lane >> 4;            // 0 or 1 -> which sample of the pair
    const int ls   = lane & 15;            // lane within half-warp
    const int gwarp  = blockIdx.x * 32 + wrp;
    const int nwarps = gridDim.x * 32;
    const int npairs = (BB * LL) / 2;

    for (int pp = gwarp; pp < npairs; pp += nwarps) {
        const int s = 2 * pp + half;

        float r = g_r[s];                                // broadcast in half-warp
        float low   = floorf(r);
        float alpha = __fsub_rn(r, low);
        int il = (int)low;
        int ih = ((int)ceilf(r)) & (LWT_ - 1);

        float4 lo = ((const float4*)(s_wt + il * WT_STRIDE))[ls];
        float4 hi = ((const float4*)(s_wt + ih * WT_STRIDE))[ls];
        float4 av = att4[(size_t)s * (WW / 4) + ls];

        float acc;
        acc = av.x * fmaf(alpha, hi.x - lo.x, lo.x);
        acc = fmaf(av.y, fmaf(alpha, hi.y - lo.y, lo.y), acc);
        acc = fmaf(av.z, fmaf(alpha, hi.z - lo.z, lo.z), acc);
        acc = fmaf(av.w, fmaf(alpha, hi.w - lo.w, lo.w), acc);

        // sum across the 16-lane group
        acc += __shfl_xor_sync(0xFFFFFFFFu, acc, 1);
        acc += __shfl_xor_sync(0xFFFFFFFFu, acc, 2);
        acc += __shfl_xor_sync(0xFFFFFFFFu, acc, 4);
        acc += __shfl_xor_sync(0xFFFFFFFFu, acc, 8);

        if (ls == 0) out[s] = acc * env[s];
    }
}

// ---------------------------------------------------------------------------
extern "C" void kernel_launch(void* const* d_in, const int* in_sizes, int n_in,
                              void* d_out, int out_size) {
    const float* pitch = (const float*)d_in[0];
    const float* env   = (const float*)d_in[1];
    const float* att   = (const float*)d_in[2];
    const float* wt    = (const float*)d_in[3];
    float* out         = (float*)d_out;

    cudaFuncSetAttribute(synth_kernel, cudaFuncAttributeMaxDynamicSharedMemorySize, MAIN_SMEM);

    k1_tilesums<<<(BB * NT1 + 255) / 256, 256>>>(pitch);
    k2_midscan<<<BB, 192>>>();
    k3_emit<<<(BB * NT1 + 255) / 256, 256>>>(pitch);
    synth_kernel<<<148, 1024, MAIN_SMEM>>>(env, (const float4*)att, wt, out);
}

// round 6
// speedup vs baseline: 2.0379x; 1.6343x over previous
#include <cuda_runtime.h>

// WavetableSynth: B=16, L=48000, W=64, LWT=512
// inputs: pitch (B*L f32), envelope (B*L f32), attention (B*L*W f32), wavetables (W*LWT f32)
// output: (B, L, 1) f32

#define BB 16
#define LL 48000
#define WW 64
#define LWT_ 512

static constexpr float K_INC = 512.0f / 16000.0f; // 0.032f in f32

#define NT1 3000   // 48000 / 16
#define NT2 188    // ceil(3000 / 16)
#define NT3 12     // ceil(188 / 16)

// scratch (no device allocations allowed; referenced ONLY from device code)
__device__ float g_G1[BB * NT1];
__device__ float g_P3[BB * NT2];
__device__ float g_r [BB * LL];    // final wavetable index per sample, in [0, 512)

// ---------------------------------------------------------------------------
// K1: tile sums G1[b][i] = sequential sum of 16 leaves RN(K*pitch), exact
// op order of the XLA radix-16 scan. One thread per tile, 48000 tiles.
// ---------------------------------------------------------------------------
__global__ void __launch_bounds__(256) k1_tilesums(const float* __restrict__ pitch) {
    int tid = blockIdx.x * blockDim.x + threadIdx.x;
    if (tid >= BB * NT1) return;
    int b = tid / NT1, i = tid - b * NT1;
    const float4* q = (const float4*)(pitch + b * LL + i * 16);
    float4 v0 = q[0], v1 = q[1], v2 = q[2], v3 = q[3];
    float lv[16] = {v0.x,v0.y,v0.z,v0.w, v1.x,v1.y,v1.z,v1.w,
                    v2.x,v2.y,v2.z,v2.w, v3.x,v3.y,v3.z,v3.w};
    float acc = __fmul_rn(K_INC, lv[0]);
    #pragma unroll
    for (int j = 1; j < 16; j++) acc = __fadd_rn(acc, __fmul_rn(K_INC, lv[j]));
    g_G1[tid] = acc;
}

// ---------------------------------------------------------------------------
// K2: per batch row — G2, G3, P4 (top scan), P3. Exact op order. Tiny.
// ---------------------------------------------------------------------------
__global__ void __launch_bounds__(192) k2_midscan() {
    __shared__ float G2[NT2], P4[NT3];
    const int b = blockIdx.x;
    const int t = threadIdx.x;
    const float* G1 = g_G1 + b * NT1;

    if (t < NT2) {
        int base = t * 16, end = min(base + 16, NT1);
        float acc = G1[base];
        for (int i = base + 1; i < end; i++) acc = __fadd_rn(acc, G1[i]);
        G2[t] = acc;
    }
    __syncthreads();
    if (t == 0) {
        float G3[NT3];
        for (int w = 0; w < NT3; w++) {
            int base = w * 16, end = min(base + 16, NT2);
            float acc = G2[base];
            for (int i = base + 1; i < end; i++) acc = __fadd_rn(acc, G2[i]);
            G3[w] = acc;
        }
        float acc = G3[0];
        P4[0] = acc;
        for (int w = 1; w < NT3; w++) { acc = __fadd_rn(acc, G3[w]); P4[w] = acc; }
    }
    __syncthreads();
    if (t < NT2) {
        int w = t >> 4, base = w * 16;
        float acc = G2[base];
        for (int i = base + 1; i <= t; i++) acc = __fadd_rn(acc, G2[i]);
        g_P3[b * NT2 + t] = (w > 0) ? __fadd_rn(P4[w - 1], acc) : acc;
    }
}

// ---------------------------------------------------------------------------
// K3: emission. One thread per tile; produces final modded index r.
// ---------------------------------------------------------------------------
__global__ void __launch_bounds__(256) k3_emit(const float* __restrict__ pitch) {
    int tid = blockIdx.x * blockDim.x + threadIdx.x;
    if (tid >= BB * NT1) return;
    int b = tid / NT1, i = tid - b * NT1;
    const float* p  = pitch + b * LL + i * 16;
    const float* p0 = pitch + i * 16;            // batch row 0 (increment[0])
    float* ro = g_r + b * LL + i * 16;

    float pref = 0.0f;
    bool has_pref = (i > 0);
    if (has_pref) {
        int j = i - 1, u = j >> 4, base = u * 16;
        const float* G1 = g_G1 + b * NT1;
        float acc = G1[base];
        for (int k = base + 1; k <= j; k++) acc = __fadd_rn(acc, G1[k]);
        pref = (u > 0) ? __fadd_rn(g_P3[b * NT2 + (u - 1)], acc) : acc;
    }

    float acc = 0.0f;
    #pragma unroll
    for (int j = 0; j < 16; j++) {
        float leaf = __fmul_rn(K_INC, p[j]);
        acc = (j == 0) ? leaf : __fadd_rn(acc, leaf);
        float cum = has_pref ? __fadd_rn(pref, acc) : acc;
        float x = fmaf(-K_INC, p0[j], cum);   // XLA contracts sub(cum, mul) -> fma
        float r = fmodf(x, 512.0f);
        if (r < 0.0f) r = __fadd_rn(r, 512.0f);
        if (__fsub_rn(512.0f, r) < 1e-5f) r = 0.0f;
        ro[j] = r;
    }
}

// ---------------------------------------------------------------------------
// K4 synth: 8-lane group per sample (lane ls owns w in [8ls, 8ls+8)); warp
// handles 4 consecutive samples per iteration. Global loads (r, attention,
// env) are software-pipelined one iteration ahead to keep LDG latency off the
// critical path. Wavetables transposed in smem [512][68] -> every 8-lane LDS
// phase reads 32 consecutive words of one row (conflict-free).
// ---------------------------------------------------------------------------
#define WT_STRIDE 68
#define MAIN_SMEM (LWT_ * WT_STRIDE * 4)
#define NQUADS (BB * LL / 4)

__global__ void __launch_bounds__(1024, 1) synth_kernel(
    const float*  __restrict__ env,
    const float4* __restrict__ att4,      // [B*L][16] float4
    const float*  __restrict__ wt,        // [64][512]
    float*        __restrict__ out)
{
    extern __shared__ float s_wt[]; // [512][WT_STRIDE]

    const int t    = threadIdx.x;
    const int lane = t & 31;
    const int wrp  = t >> 5;          // 32 warps/CTA
    // transpose: warp per wavetable row, coalesced float4 reads
    for (int w = wrp; w < WW; w += 32) {
        const float4* row = (const float4*)(wt + w * LWT_);
        for (int c4 = lane; c4 < LWT_ / 4; c4 += 32) {
            float4 v = row[c4];
            int idx = c4 * 4;
            s_wt[(idx + 0) * WT_STRIDE + w] = v.x;
            s_wt[(idx + 1) * WT_STRIDE + w] = v.y;
            s_wt[(idx + 2) * WT_STRIDE + w] = v.z;
            s_wt[(idx + 3) * WT_STRIDE + w] = v.w;
        }
    }
    __syncthreads();

    const int grp = lane >> 3;             // 0..3: which sample of the quad
    const int ls  = lane & 7;              // lane within 8-lane group
    const int gwarp  = blockIdx.x * 32 + wrp;
    const int nwarps = gridDim.x * 32;

    int q = gwarp;                         // quad index
    // -------- prologue: load iteration 0 --------
    float  r_c, e_c;
    float4 a0_c, a1_c;
    {
        int s = 4 * q + grp;
        r_c = g_r[s];
        e_c = env[s];
        const float4* ap = att4 + (size_t)s * (WW / 4);
        a0_c = ap[2 * ls];
        a1_c = ap[2 * ls + 1];
    }

    while (q < NQUADS) {
        const int qn = q + nwarps;
        // -------- prefetch next iteration's globals --------
        float  r_n = 0.0f, e_n = 0.0f;
        float4 a0_n = {}, a1_n = {};
        if (qn < NQUADS) {
            int sn = 4 * qn + grp;
            r_n = g_r[sn];
            e_n = env[sn];
            const float4* ap = att4 + (size_t)sn * (WW / 4);
            a0_n = ap[2 * ls];
            a1_n = ap[2 * ls + 1];
        }

        // -------- compute current --------
        float low   = floorf(r_c);
        float alpha = __fsub_rn(r_c, low);
        int il = (int)low;
        int ih = ((int)ceilf(r_c)) & (LWT_ - 1);

        const float4* wl = (const float4*)(s_wt + il * WT_STRIDE);
        const float4* wh = (const float4*)(s_wt + ih * WT_STRIDE);
        float4 lo0 = wl[2 * ls], lo1 = wl[2 * ls + 1];
        float4 hi0 = wh[2 * ls], hi1 = wh[2 * ls + 1];

        float acc;
        acc = a0_c.x * fmaf(alpha, hi0.x - lo0.x, lo0.x);
        acc = fmaf(a0_c.y, fmaf(alpha, hi0.y - lo0.y, lo0.y), acc);
        acc = fmaf(a0_c.z, fmaf(alpha, hi0.z - lo0.z, lo0.z), acc);
        acc = fmaf(a0_c.w, fmaf(alpha, hi0.w - lo0.w, lo0.w), acc);
        acc = fmaf(a1_c.x, fmaf(alpha, hi1.x - lo1.x, lo1.x), acc);
        acc = fmaf(a1_c.y, fmaf(alpha, hi1.y - lo1.y, lo1.y), acc);
        acc = fmaf(a1_c.z, fmaf(alpha, hi1.z - lo1.z, lo1.z), acc);
        acc = fmaf(a1_c.w, fmaf(alpha, hi1.w - lo1.w, lo1.w), acc);

        // reduce across the 8-lane group
        acc += __shfl_xor_sync(0xFFFFFFFFu, acc, 1);
        acc += __shfl_xor_sync(0xFFFFFFFFu, acc, 2);
        acc += __shfl_xor_sync(0xFFFFFFFFu, acc, 4);

        if (ls == 0) out[4 * q + grp] = acc * e_c;   // 4 consecutive floats/warp

        // rotate pipeline
        r_c = r_n; e_c = e_n; a0_c = a0_n; a1_c = a1_n;
        q = qn;
    }
}

// ---------------------------------------------------------------------------
extern "C" void kernel_launch(void* const* d_in, const int* in_sizes, int n_in,
                              void* d_out, int out_size) {
    const float* pitch = (const float*)d_in[0];
    const float* env   = (const float*)d_in[1];
    const float* att   = (const float*)d_in[2];
    const float* wt    = (const float*)d_in[3];
    float* out         = (float*)d_out;

    cudaFuncSetAttribute(synth_kernel, cudaFuncAttributeMaxDynamicSharedMemorySize, MAIN_SMEM);

    k1_tilesums<<<(BB * NT1 + 255) / 256, 256>>>(pitch);
    k2_midscan<<<BB, 192>>>();
    k3_emit<<<(BB * NT1 + 255) / 256, 256>>>(pitch);
    synth_kernel<<<148, 1024, MAIN_SMEM>>>(env, (const float4*)att, wt, out);
}

// round 7
// speedup vs baseline: 2.2845x; 1.1210x over previous
#include <cuda_runtime.h>

// WavetableSynth: B=16, L=48000, W=64, LWT=512
// inputs: pitch (B*L f32), envelope (B*L f32), attention (B*L*W f32), wavetables (W*LWT f32)
// output: (B, L, 1) f32

#define BB 16
#define LL 48000
#define WW 64
#define LWT_ 512

static constexpr float K_INC = 512.0f / 16000.0f; // 0.032f in f32

#define NT1 3000   // 48000 / 16 tiles per row
#define NT2 188    // ceil(3000 / 16)
#define NT3 12     // ceil(188 / 16)

#define TPW 11                 // tiles per warp chunk
#define SPW (TPW * 16)         // 176 samples per chunk
#define CHUNKS_PER_ROW 273     // ceil(3000 / 11); last chunk = 8 tiles
#define NCHUNKS (BB * CHUNKS_PER_ROW)   // 4368

// scratch (referenced ONLY from device code)
__device__ float g_G1[BB * NT1];
__device__ float g_P3[BB * NT2];

// ---------------------------------------------------------------------------
// scan_kernel: fused k1+k2. One CTA per batch row (16 CTAs x 1024).
// G1 tile sums, G2, G3, P4 top scan, P3 — exact XLA radix-16 op order.
// ---------------------------------------------------------------------------
__global__ void __launch_bounds__(1024, 1) scan_kernel(const float* __restrict__ pitch) {
    __shared__ float sG1[NT1];
    __shared__ float sG2[NT2], sP4[NT3];
    const int b = blockIdx.x;
    const int t = threadIdx.x;
    const float* p = pitch + b * LL;

    // G1: each thread ~3 tiles
    for (int i = t; i < NT1; i += 1024) {
        const float4* q = (const float4*)(p + i * 16);
        float4 v0 = q[0], v1 = q[1], v2 = q[2], v3 = q[3];
        float lv[16] = {v0.x,v0.y,v0.z,v0.w, v1.x,v1.y,v1.z,v1.w,
                        v2.x,v2.y,v2.z,v2.w, v3.x,v3.y,v3.z,v3.w};
        float acc = __fmul_rn(K_INC, lv[0]);
        #pragma unroll
        for (int j = 1; j < 16; j++) acc = __fadd_rn(acc, __fmul_rn(K_INC, lv[j]));
        sG1[i] = acc;
        g_G1[b * NT1 + i] = acc;
    }
    __syncthreads();

    if (t < NT2) {
        int base = t * 16, end = min(base + 16, NT1);
        float acc = sG1[base];
        for (int i = base + 1; i < end; i++) acc = __fadd_rn(acc, sG1[i]);
        sG2[t] = acc;
    }
    __syncthreads();
    if (t == 0) {
        float G3[NT3];
        for (int w = 0; w < NT3; w++) {
            int base = w * 16, end = min(base + 16, NT2);
            float acc = sG2[base];
            for (int i = base + 1; i < end; i++) acc = __fadd_rn(acc, sG2[i]);
            G3[w] = acc;
        }
        float acc = G3[0];
        sP4[0] = acc;
        for (int w = 1; w < NT3; w++) { acc = __fadd_rn(acc, G3[w]); sP4[w] = acc; }
    }
    __syncthreads();
    if (t < NT2) {
        int w = t >> 4, base = w * 16;
        float acc = sG2[base];
        for (int i = base + 1; i <= t; i++) acc = __fadd_rn(acc, sG2[i]);
        g_P3[b * NT2 + t] = (w > 0) ? __fadd_rn(sP4[w - 1], acc) : acc;
    }
}

// ---------------------------------------------------------------------------
// synth: warp owns a contiguous 11-tile (176-sample) chunk of one batch row.
// Phase A: lanes 0..ntiles-1 each run one tile's leaf scan (exact k3 op
//          order) producing r into smem.
// Phase B: 8-lane group per sample, 4 samples/warp/iter, depth-1 prefetch.
//          Lane ls owns w in {4ls..4ls+3} u {32+4ls..32+4ls+3} so every
//          8-lane LDS/LDG phase is one contiguous 128B window.
// ---------------------------------------------------------------------------
#define WT_STRIDE 68
#define SMEM_R_OFF (LWT_ * WT_STRIDE)                 // floats
#define MAIN_SMEM ((LWT_ * WT_STRIDE + 32 * SPW) * 4) // table + per-warp r

__global__ void __launch_bounds__(1024, 1) synth_kernel(
    const float*  __restrict__ pitch,
    const float*  __restrict__ env,
    const float4* __restrict__ att4,      // [B*L][16] float4
    const float*  __restrict__ wt,        // [64][512]
    float*        __restrict__ out)
{
    extern __shared__ float s_wt[]; // [512][WT_STRIDE] then r[32][176]

    const int t    = threadIdx.x;
    const int lane = t & 31;
    const int wrp  = t >> 5;          // 32 warps/CTA
    // transpose: warp per wavetable row, coalesced float4 reads
    for (int w = wrp; w < WW; w += 32) {
        const float4* row = (const float4*)(wt + w * LWT_);
        for (int c4 = lane; c4 < LWT_ / 4; c4 += 32) {
            float4 v = row[c4];
            int idx = c4 * 4;
            s_wt[(idx + 0) * WT_STRIDE + w] = v.x;
            s_wt[(idx + 1) * WT_STRIDE + w] = v.y;
            s_wt[(idx + 2) * WT_STRIDE + w] = v.z;
            s_wt[(idx + 3) * WT_STRIDE + w] = v.w;
        }
    }
    __syncthreads();

    const int gwarp = blockIdx.x * 32 + wrp;   // chunk id
    if (gwarp >= NCHUNKS) return;

    const int b  = gwarp / CHUNKS_PER_ROW;
    const int k  = gwarp - b * CHUNKS_PER_ROW;
    const int first_tile = k * TPW;
    const int ntiles = min(TPW, NT1 - first_tile);
    const int s0 = b * LL + first_tile * 16;   // global first sample

    float* s_r = s_wt + SMEM_R_OFF + wrp * SPW;

    // -------- Phase A: per-tile scans (lane li handles tile first_tile+li) --
    if (lane < ntiles) {
        const int i = first_tile + lane;
        const float* p  = pitch + b * LL + i * 16;
        const float* p0 = pitch + i * 16;            // batch row 0
        const float* G1 = g_G1 + b * NT1;

        float pref = 0.0f;
        bool has_pref = (i > 0);
        if (has_pref) {
            int j = i - 1, u = j >> 4, base = u * 16;
            float acc = G1[base];
            for (int kk = base + 1; kk <= j; kk++) acc = __fadd_rn(acc, G1[kk]);
            pref = (u > 0) ? __fadd_rn(g_P3[b * NT2 + (u - 1)], acc) : acc;
        }

        float acc = 0.0f;
        #pragma unroll
        for (int j = 0; j < 16; j++) {
            float leaf = __fmul_rn(K_INC, p[j]);
            acc = (j == 0) ? leaf : __fadd_rn(acc, leaf);
            float cum = has_pref ? __fadd_rn(pref, acc) : acc;
            float x = fmaf(-K_INC, p0[j], cum);  // XLA: sub(cum, mul) -> fma
            float r = fmodf(x, 512.0f);
            if (r < 0.0f) r = __fadd_rn(r, 512.0f);
            if (__fsub_rn(512.0f, r) < 1e-5f) r = 0.0f;
            s_r[lane * 16 + j] = r;
        }
    }
    __syncwarp();

    // -------- Phase B: quad loop with depth-1 prefetch --------
    const int grp = lane >> 3;             // sample within quad
    const int ls  = lane & 7;
    const int nq  = ntiles * 4;            // quads in this chunk (44 or 32)

    float  e_c;
    float4 a0_c, a1_c;
    {
        int s = s0 + grp;
        e_c = env[s];
        const float4* ap = att4 + (size_t)s * (WW / 4);
        a0_c = ap[ls];
        a1_c = ap[ls + 8];
    }

    for (int q = 0; q < nq; q++) {
        // prefetch next quad's globals
        float  e_n = 0.0f;
        float4 a0_n = {}, a1_n = {};
        if (q + 1 < nq) {
            int sn = s0 + 4 * (q + 1) + grp;
            e_n = env[sn];
            const float4* ap = att4 + (size_t)sn * (WW / 4);
            a0_n = ap[ls];
            a1_n = ap[ls + 8];
        }

        float r = s_r[4 * q + grp];
        float low   = floorf(r);
        float alpha = __fsub_rn(r, low);
        int il = (int)low;
        int ih = ((int)ceilf(r)) & (LWT_ - 1);

        const float4* wl = (const float4*)(s_wt + il * WT_STRIDE);
        const float4* wh = (const float4*)(s_wt + ih * WT_STRIDE);
        float4 lo0 = wl[ls], lo1 = wl[ls + 8];
        float4 hi0 = wh[ls], hi1 = wh[ls + 8];

        float acc;
        acc = a0_c.x * fmaf(alpha, hi0.x - lo0.x, lo0.x);
        acc = fmaf(a0_c.y, fmaf(alpha, hi0.y - lo0.y, lo0.y), acc);
        acc = fmaf(a0_c.z, fmaf(alpha, hi0.z - lo0.z, lo0.z), acc);
        acc = fmaf(a0_c.w, fmaf(alpha, hi0.w - lo0.w, lo0.w), acc);
        acc = fmaf(a1_c.x, fmaf(alpha, hi1.x - lo1.x, lo1.x), acc);
        acc = fmaf(a1_c.y, fmaf(alpha, hi1.y - lo1.y, lo1.y), acc);
        acc = fmaf(a1_c.z, fmaf(alpha, hi1.z - lo1.z, lo1.z), acc);
        acc = fmaf(a1_c.w, fmaf(alpha, hi1.w - lo1.w, lo1.w), acc);

        acc += __shfl_xor_sync(0xFFFFFFFFu, acc, 1);
        acc += __shfl_xor_sync(0xFFFFFFFFu, acc, 2);
        acc += __shfl_xor_sync(0xFFFFFFFFu, acc, 4);

        if (ls == 0) out[s0 + 4 * q + grp] = acc * e_c;

        e_c = e_n; a0_c = a0_n; a1_c = a1_n;
    }
}

// ---------------------------------------------------------------------------
extern "C" void kernel_launch(void* const* d_in, const int* in_sizes, int n_in,
                              void* d_out, int out_size) {
    const float* pitch = (const float*)d_in[0];
    const float* env   = (const float*)d_in[1];
    const float* att   = (const float*)d_in[2];
    const float* wt    = (const float*)d_in[3];
    float* out         = (float*)d_out;

    cudaFuncSetAttribute(synth_kernel, cudaFuncAttributeMaxDynamicSharedMemorySize, MAIN_SMEM);

    scan_kernel<<<BB, 1024>>>(pitch);
    synth_kernel<<<148, 1024, MAIN_SMEM>>>(pitch, env, (const float4*)att, wt, out);
}

// round 10
// speedup vs baseline: 2.6198x; 1.1468x over previous
#include <cuda_runtime.h>

// WavetableSynth: B=16, L=48000, W=64, LWT=512
// inputs: pitch (B*L f32), envelope (B*L f32), attention (B*L*W f32), wavetables (W*LWT f32)
// output: (B, L, 1) f32

#define BB 16
#define LL 48000
#define WW 64
#define LWT_ 512

static constexpr float K_INC = 512.0f / 16000.0f; // 0.032f in f32

#define NT1 3000   // 48000 / 16 tiles per row
#define NT2 188    // ceil(3000 / 16)
#define NT3 12     // ceil(188 / 16)

#define TPW 11                 // tiles per warp chunk
#define SPW (TPW * 16)         // 176 samples per chunk
#define CHUNKS_PER_ROW 273     // ceil(3000 / 11); last chunk = 8 tiles
#define NCHUNKS (BB * CHUNKS_PER_ROW)   // 4368

// scratch (referenced ONLY from device code)
__device__ float g_G1[BB * NT1];
__device__ float g_P3[BB * NT2];

// ---------------------------------------------------------------------------
// K1: tile sums G1 (full-grid, one thread per tile) — exact XLA op order.
// ---------------------------------------------------------------------------
__global__ void __launch_bounds__(256) k1_tilesums(const float* __restrict__ pitch) {
    int tid = blockIdx.x * blockDim.x + threadIdx.x;
    if (tid >= BB * NT1) return;
    int b = tid / NT1, i = tid - b * NT1;
    const float4* q = (const float4*)(pitch + b * LL + i * 16);
    float4 v0 = q[0], v1 = q[1], v2 = q[2], v3 = q[3];
    float lv[16] = {v0.x,v0.y,v0.z,v0.w, v1.x,v1.y,v1.z,v1.w,
                    v2.x,v2.y,v2.z,v2.w, v3.x,v3.y,v3.z,v3.w};
    float acc = __fmul_rn(K_INC, lv[0]);
    #pragma unroll
    for (int j = 1; j < 16; j++) acc = __fadd_rn(acc, __fmul_rn(K_INC, lv[j]));
    g_G1[tid] = acc;
}

// ---------------------------------------------------------------------------
// K2: per batch row — G2, G3, P4 top scan, P3. Exact op order. Tiny.
// ---------------------------------------------------------------------------
__global__ void __launch_bounds__(192) k2_midscan() {
    __shared__ float G2[NT2], P4[NT3];
    const int b = blockIdx.x;
    const int t = threadIdx.x;
    const float* G1 = g_G1 + b * NT1;

    if (t < NT2) {
        int base = t * 16, end = min(base + 16, NT1);
        float acc = G1[base];
        for (int i = base + 1; i < end; i++) acc = __fadd_rn(acc, G1[i]);
        G2[t] = acc;
    }
    __syncthreads();
    if (t == 0) {
        float G3[NT3];
        for (int w = 0; w < NT3; w++) {
            int base = w * 16, end = min(base + 16, NT2);
            float acc = G2[base];
            for (int i = base + 1; i < end; i++) acc = __fadd_rn(acc, G2[i]);
            G3[w] = acc;
        }
        float acc = G3[0];
        P4[0] = acc;
        for (int w = 1; w < NT3; w++) { acc = __fadd_rn(acc, G3[w]); P4[w] = acc; }
    }
    __syncthreads();
    if (t < NT2) {
        int w = t >> 4, base = w * 16;
        float acc = G2[base];
        for (int i = base + 1; i <= t; i++) acc = __fadd_rn(acc, G2[i]);
        g_P3[b * NT2 + t] = (w > 0) ? __fadd_rn(P4[w - 1], acc) : acc;
    }
}

// ---------------------------------------------------------------------------
// synth: warp owns a contiguous 11-tile (176-sample) chunk of one batch row.
// Phase A: lanes 0..ntiles-1 each run one tile's leaf scan (exact k3 op
//          order) producing r into smem.
// Phase B: 8-lane group per sample; TWO quads (8 samples) per loop iteration
//          with the next pair's globals prefetched -> two independent
//          LDS/FMA/SHFL chains in flight per warp.
// ---------------------------------------------------------------------------
#define WT_STRIDE 68
#define SMEM_R_OFF (LWT_ * WT_STRIDE)                 // floats
#define MAIN_SMEM ((LWT_ * WT_STRIDE + 32 * SPW) * 4) // table + per-warp r

__global__ void __launch_bounds__(1024, 1) synth_kernel(
    const float*  __restrict__ pitch,
    const float*  __restrict__ env,
    const float4* __restrict__ att4,      // [B*L][16] float4
    const float*  __restrict__ wt,        // [64][512]
    float*        __restrict__ out)
{
    extern __shared__ float s_wt[]; // [512][WT_STRIDE] then r[32][176]

    const int t    = threadIdx.x;
    const int lane = t & 31;
    const int wrp  = t >> 5;          // 32 warps/CTA
    for (int w = wrp; w < WW; w += 32) {
        const float4* row = (const float4*)(wt + w * LWT_);
        for (int c4 = lane; c4 < LWT_ / 4; c4 += 32) {
            float4 v = row[c4];
            int idx = c4 * 4;
            s_wt[(idx + 0) * WT_STRIDE + w] = v.x;
            s_wt[(idx + 1) * WT_STRIDE + w] = v.y;
            s_wt[(idx + 2) * WT_STRIDE + w] = v.z;
            s_wt[(idx + 3) * WT_STRIDE + w] = v.w;
        }
    }
    __syncthreads();

    const int gwarp = blockIdx.x * 32 + wrp;   // chunk id
    if (gwarp >= NCHUNKS) return;

    const int b  = gwarp / CHUNKS_PER_ROW;
    const int k  = gwarp - b * CHUNKS_PER_ROW;
    const int first_tile = k * TPW;
    const int ntiles = min(TPW, NT1 - first_tile);
    const int s0 = b * LL + first_tile * 16;   // global first sample

    float* s_r = s_wt + SMEM_R_OFF + wrp * SPW;

    // -------- Phase A: per-tile scans --------
    if (lane < ntiles) {
        const int i = first_tile + lane;
        const float* p  = pitch + b * LL + i * 16;
        const float* p0 = pitch + i * 16;            // batch row 0
        const float* G1 = g_G1 + b * NT1;

        float pref = 0.0f;
        bool has_pref = (i > 0);
        if (has_pref) {
            int j = i - 1, u = j >> 4, base = u * 16;
            float acc = G1[base];
            for (int kk = base + 1; kk <= j; kk++) acc = __fadd_rn(acc, G1[kk]);
            pref = (u > 0) ? __fadd_rn(g_P3[b * NT2 + (u - 1)], acc) : acc;
        }

        float acc = 0.0f;
        #pragma unroll
        for (int j = 0; j < 16; j++) {
            float leaf = __fmul_rn(K_INC, p[j]);
            acc = (j == 0) ? leaf : __fadd_rn(acc, leaf);
            float cum = has_pref ? __fadd_rn(pref, acc) : acc;
            float x = fmaf(-K_INC, p0[j], cum);  // XLA: sub(cum, mul) -> fma
            float r = fmodf(x, 512.0f);
            if (r < 0.0f) r = __fadd_rn(r, 512.0f);
            if (__fsub_rn(512.0f, r) < 1e-5f) r = 0.0f;
            s_r[lane * 16 + j] = r;
        }
    }
    __syncwarp();

    // -------- Phase B: pair-of-quads loop with prefetch --------
    const int grp = lane >> 3;             // sample within quad
    const int ls  = lane & 7;
    const int nq  = ntiles * 4;            // 44 or 32 (always even)

    float  e0_c, e1_c;
    float4 a00_c, a01_c, a10_c, a11_c;
    {
        int sA = s0 + grp, sB = s0 + 4 + grp;
        e0_c = env[sA];  e1_c = env[sB];
        const float4* apA = att4 + (size_t)sA * (WW / 4);
        const float4* apB = att4 + (size_t)sB * (WW / 4);
        a00_c = __ldcs(apA + ls);  a01_c = __ldcs(apA + ls + 8);
        a10_c = __ldcs(apB + ls);  a11_c = __ldcs(apB + ls + 8);
    }

    for (int q = 0; q < nq; q += 2) {
        // prefetch next pair
        float  e0_n = 0.0f, e1_n = 0.0f;
        float4 a00_n = {}, a01_n = {}, a10_n = {}, a11_n = {};
        if (q + 2 < nq) {
            int sA = s0 + 4 * (q + 2) + grp, sB = s0 + 4 * (q + 3) + grp;
            e0_n = env[sA];  e1_n = env[sB];
            const float4* apA = att4 + (size_t)sA * (WW / 4);
            const float4* apB = att4 + (size_t)sB * (WW / 4);
            a00_n = __ldcs(apA + ls);  a01_n = __ldcs(apA + ls + 8);
            a10_n = __ldcs(apB + ls);  a11_n = __ldcs(apB + ls + 8);
        }

        // --- sample stream 0 (quad q) ---
        float rA = s_r[4 * q + grp];
        float lowA = floorf(rA);
        float alA  = __fsub_rn(rA, lowA);
        int ilA = (int)lowA;
        int ihA = ((int)ceilf(rA)) & (LWT_ - 1);
        const float4* wlA = (const float4*)(s_wt + ilA * WT_STRIDE);
        const float4* whA = (const float4*)(s_wt + ihA * WT_STRIDE);
        float4 loA0 = wlA[ls], loA1 = wlA[ls + 8];
        float4 hiA0 = whA[ls], hiA1 = whA[ls + 8];

        // --- sample stream 1 (quad q+1) ---
        float rB = s_r[4 * (q + 1) + grp];
        float lowB = floorf(rB);
        float alB  = __fsub_rn(rB, lowB);
        int ilB = (int)lowB;
        int ihB = ((int)ceilf(rB)) & (LWT_ - 1);
        const float4* wlB = (const float4*)(s_wt + ilB * WT_STRIDE);
        const float4* whB = (const float4*)(s_wt + ihB * WT_STRIDE);
        float4 loB0 = wlB[ls], loB1 = wlB[ls + 8];
        float4 hiB0 = whB[ls], hiB1 = whB[ls + 8];

        float accA;
        accA = a00_c.x * fmaf(alA, hiA0.x - loA0.x, loA0.x);
        accA = fmaf(a00_c.y, fmaf(alA, hiA0.y - loA0.y, loA0.y), accA);
        accA = fmaf(a00_c.z, fmaf(alA, hiA0.z - loA0.z, loA0.z), accA);
        accA = fmaf(a00_c.w, fmaf(alA, hiA0.w - loA0.w, loA0.w), accA);
        accA = fmaf(a01_c.x, fmaf(alA, hiA1.x - loA1.x, loA1.x), accA);
        accA = fmaf(a01_c.y, fmaf(alA, hiA1.y - loA1.y, loA1.y), accA);
        accA = fmaf(a01_c.z, fmaf(alA, hiA1.z - loA1.z, loA1.z), accA);
        accA = fmaf(a01_c.w, fmaf(alA, hiA1.w - loA1.w, loA1.w), accA);

        float accB;
        accB = a10_c.x * fmaf(alB, hiB0.x - loB0.x, loB0.x);
        accB = fmaf(a10_c.y, fmaf(alB, hiB0.y - loB0.y, loB0.y), accB);
        accB = fmaf(a10_c.z, fmaf(alB, hiB0.z - loB0.z, loB0.z), accB);
        accB = fmaf(a10_c.w, fmaf(alB, hiB0.w - loB0.w, loB0.w), accB);
        accB = fmaf(a11_c.x, fmaf(alB, hiB1.x - loB1.x, loB1.x), accB);
        accB = fmaf(a11_c.y, fmaf(alB, hiB1.y - loB1.y, loB1.y), accB);
        accB = fmaf(a11_c.z, fmaf(alB, hiB1.z - loB1.z, loB1.z), accB);
        accB = fmaf(a11_c.w, fmaf(alB, hiB1.w - loB1.w, loB1.w), accB);

        accA += __shfl_xor_sync(0xFFFFFFFFu, accA, 1);
        accB += __shfl_xor_sync(0xFFFFFFFFu, accB, 1);
        accA += __shfl_xor_sync(0xFFFFFFFFu, accA, 2);
        accB += __shfl_xor_sync(0xFFFFFFFFu, accB, 2);
        accA += __shfl_xor_sync(0xFFFFFFFFu, accA, 4);
        accB += __shfl_xor_sync(0xFFFFFFFFu, accB, 4);

        if (ls == 0) {
            out[s0 + 4 * q + grp]       = accA * e0_c;
            out[s0 + 4 * (q + 1) + grp] = accB * e1_c;
        }

        e0_c = e0_n; e1_c = e1_n;
        a00_c = a00_n; a01_c = a01_n; a10_c = a10_n; a11_c = a11_n;
    }
}

// ---------------------------------------------------------------------------
extern "C" void kernel_launch(void* const* d_in, const int* in_sizes, int n_in,
                              void* d_out, int out_size) {
    const float* pitch = (const float*)d_in[0];
    const float* env   = (const float*)d_in[1];
    const float* att   = (const float*)d_in[2];
    const float* wt    = (const float*)d_in[3];
    float* out         = (float*)d_out;

    cudaFuncSetAttribute(synth_kernel, cudaFuncAttributeMaxDynamicSharedMemorySize, MAIN_SMEM);

    k1_tilesums<<<(BB * NT1 + 255) / 256, 256>>>(pitch);
    k2_midscan<<<BB, 192>>>();
    synth_kernel<<<148, 1024, MAIN_SMEM>>>(pitch, env, (const float4*)att, wt, out);
}

// round 11
// speedup vs baseline: 2.6533x; 1.0128x over previous
#include <cuda_runtime.h>

// WavetableSynth: B=16, L=48000, W=64, LWT=512
// inputs: pitch (B*L f32), envelope (B*L f32), attention (B*L*W f32), wavetables (W*LWT f32)
// output: (B, L, 1) f32

#define BB 16
#define LL 48000
#define WW 64
#define LWT_ 512

static constexpr float K_INC = 512.0f / 16000.0f; // 0.032f in f32

#define NT1 3000   // 48000 / 16 tiles per row
#define NT2 188    // ceil(3000 / 16)
#define NT3 12     // ceil(188 / 16)

#define TPW 11                 // tiles per warp chunk
#define SPW (TPW * 16)         // 176 samples per chunk
#define CHUNKS_PER_ROW 273     // ceil(3000 / 11); last chunk = 8 tiles
#define NCHUNKS (BB * CHUNKS_PER_ROW)   // 4368

// scratch (referenced ONLY from device code)
__device__ float g_G1[BB * NT1];
__device__ float g_P3[BB * NT2];

// ---------------------------------------------------------------------------
// K1: tile sums G1 (one thread per tile) — exact XLA op order.
// ---------------------------------------------------------------------------
__global__ void __launch_bounds__(128) k1_tilesums(const float* __restrict__ pitch) {
    int tid = blockIdx.x * blockDim.x + threadIdx.x;
    if (tid >= BB * NT1) return;
    int b = tid / NT1, i = tid - b * NT1;
    const float4* q = (const float4*)(pitch + b * LL + i * 16);
    float4 v0 = q[0], v1 = q[1], v2 = q[2], v3 = q[3];
    float lv[16] = {v0.x,v0.y,v0.z,v0.w, v1.x,v1.y,v1.z,v1.w,
                    v2.x,v2.y,v2.z,v2.w, v3.x,v3.y,v3.z,v3.w};
    float acc = __fmul_rn(K_INC, lv[0]);
    #pragma unroll
    for (int j = 1; j < 16; j++) acc = __fadd_rn(acc, __fmul_rn(K_INC, lv[j]));
    g_G1[tid] = acc;
}

// ---------------------------------------------------------------------------
// K2: per batch row — G2, G3, P4 top scan, P3. Exact op order. Tiny.
// ---------------------------------------------------------------------------
__global__ void __launch_bounds__(192) k2_midscan() {
    __shared__ float G2[NT2], P4[NT3];
    const int b = blockIdx.x;
    const int t = threadIdx.x;
    const float* G1 = g_G1 + b * NT1;

    if (t < NT2) {
        int base = t * 16, end = min(base + 16, NT1);
        float acc = G1[base];
        for (int i = base + 1; i < end; i++) acc = __fadd_rn(acc, G1[i]);
        G2[t] = acc;
    }
    __syncthreads();
    if (t == 0) {
        float G3[NT3];
        for (int w = 0; w < NT3; w++) {
            int base = w * 16, end = min(base + 16, NT2);
            float acc = G2[base];
            for (int i = base + 1; i < end; i++) acc = __fadd_rn(acc, G2[i]);
            G3[w] = acc;
        }
        float acc = G3[0];
        P4[0] = acc;
        for (int w = 1; w < NT3; w++) { acc = __fadd_rn(acc, G3[w]); P4[w] = acc; }
    }
    __syncthreads();
    if (t < NT2) {
        int w = t >> 4, base = w * 16;
        float acc = G2[base];
        for (int i = base + 1; i <= t; i++) acc = __fadd_rn(acc, G2[i]);
        g_P3[b * NT2 + t] = (w > 0) ? __fadd_rn(P4[w - 1], acc) : acc;
    }
}

// ---------------------------------------------------------------------------
// synth: warp owns a contiguous 11-tile (176-sample) chunk of one batch row.
// Phase A: lanes 0..ntiles-1 run one tile scan each (exact k3 op order) -> r.
// Phase B: 8-lane group/sample, 2 quads/iter, depth-1 register prefetch for
//          att/env/r, plus prefetch.global.L2 at 3-iteration distance so the
//          register prefetch hits L2 instead of backpressured DRAM.
// ---------------------------------------------------------------------------
#define WT_STRIDE 68
#define SMEM_R_OFF (LWT_ * WT_STRIDE)                 // floats
#define MAIN_SMEM ((LWT_ * WT_STRIDE + 32 * SPW) * 4) // table + per-warp r

__global__ void __launch_bounds__(1024, 1) synth_kernel(
    const float*  __restrict__ pitch,
    const float*  __restrict__ env,
    const float4* __restrict__ att4,      // [B*L][16] float4
    const float*  __restrict__ wt,        // [64][512]
    float*        __restrict__ out)
{
    extern __shared__ float s_wt[]; // [512][WT_STRIDE] then r[32][176]

    const int t    = threadIdx.x;
    const int lane = t & 31;
    const int wrp  = t >> 5;          // 32 warps/CTA
    for (int w = wrp; w < WW; w += 32) {
        const float4* row = (const float4*)(wt + w * LWT_);
        for (int c4 = lane; c4 < LWT_ / 4; c4 += 32) {
            float4 v = row[c4];
            int idx = c4 * 4;
            s_wt[(idx + 0) * WT_STRIDE + w] = v.x;
            s_wt[(idx + 1) * WT_STRIDE + w] = v.y;
            s_wt[(idx + 2) * WT_STRIDE + w] = v.z;
            s_wt[(idx + 3) * WT_STRIDE + w] = v.w;
        }
    }
    __syncthreads();

    const int gwarp = blockIdx.x * 32 + wrp;   // chunk id
    if (gwarp >= NCHUNKS) return;

    const int b  = gwarp / CHUNKS_PER_ROW;
    const int k  = gwarp - b * CHUNKS_PER_ROW;
    const int first_tile = k * TPW;
    const int ntiles = min(TPW, NT1 - first_tile);
    const int s0 = b * LL + first_tile * 16;   // global first sample

    float* s_r = s_wt + SMEM_R_OFF + wrp * SPW;

    // -------- Phase A: per-tile scans --------
    if (lane < ntiles) {
        const int i = first_tile + lane;
        const float* p  = pitch + b * LL + i * 16;
        const float* p0 = pitch + i * 16;            // batch row 0
        const float* G1 = g_G1 + b * NT1;

        float pref = 0.0f;
        bool has_pref = (i > 0);
        if (has_pref) {
            int j = i - 1, u = j >> 4, base = u * 16;
            float acc = G1[base];
            for (int kk = base + 1; kk <= j; kk++) acc = __fadd_rn(acc, G1[kk]);
            pref = (u > 0) ? __fadd_rn(g_P3[b * NT2 + (u - 1)], acc) : acc;
        }

        float acc = 0.0f;
        #pragma unroll
        for (int j = 0; j < 16; j++) {
            float leaf = __fmul_rn(K_INC, p[j]);
            acc = (j == 0) ? leaf : __fadd_rn(acc, leaf);
            float cum = has_pref ? __fadd_rn(pref, acc) : acc;
            float x = fmaf(-K_INC, p0[j], cum);  // XLA: sub(cum, mul) -> fma
            float r = fmodf(x, 512.0f);
            if (r < 0.0f) r = __fadd_rn(r, 512.0f);
            if (__fsub_rn(512.0f, r) < 1e-5f) r = 0.0f;
            s_r[lane * 16 + j] = r;
        }
    }
    __syncwarp();

    // -------- Phase B: pair-of-quads loop with prefetch --------
    const int grp = lane >> 3;             // sample within quad
    const int ls  = lane & 7;
    const int nq  = ntiles * 4;            // 44 or 32 (always even)

    float  e0_c, e1_c, r0_c, r1_c;
    float4 a00_c, a01_c, a10_c, a11_c;
    {
        int sA = s0 + grp, sB = s0 + 4 + grp;
        e0_c = env[sA];  e1_c = env[sB];
        r0_c = s_r[grp]; r1_c = s_r[4 + grp];
        const float4* apA = att4 + (size_t)sA * (WW / 4);
        const float4* apB = att4 + (size_t)sB * (WW / 4);
        a00_c = __ldcs(apA + ls);  a01_c = __ldcs(apA + ls + 8);
        a10_c = __ldcs(apB + ls);  a11_c = __ldcs(apB + ls + 8);
    }

    for (int q = 0; q < nq; q += 2) {
        // L2 prefetch 3 iterations ahead (att only; request/consume decoupled)
        if (q + 6 < nq) {
            const float4* pfA = att4 + (size_t)(s0 + 4 * (q + 6) + grp) * (WW / 4);
            asm volatile("prefetch.global.L2 [%0];" :: "l"(pfA + ls));
            asm volatile("prefetch.global.L2 [%0];" :: "l"(pfA + ls + 8));
        }
        if (q + 7 < nq) {
            const float4* pfB = att4 + (size_t)(s0 + 4 * (q + 7) + grp) * (WW / 4);
            asm volatile("prefetch.global.L2 [%0];" :: "l"(pfB + ls));
            asm volatile("prefetch.global.L2 [%0];" :: "l"(pfB + ls + 8));
        }

        // register prefetch for next pair
        float  e0_n = 0.0f, e1_n = 0.0f, r0_n = 0.0f, r1_n = 0.0f;
        float4 a00_n = {}, a01_n = {}, a10_n = {}, a11_n = {};
        if (q + 2 < nq) {
            int sA = s0 + 4 * (q + 2) + grp, sB = s0 + 4 * (q + 3) + grp;
            e0_n = env[sA];  e1_n = env[sB];
            r0_n = s_r[4 * (q + 2) + grp]; r1_n = s_r[4 * (q + 3) + grp];
            const float4* apA = att4 + (size_t)sA * (WW / 4);
            const float4* apB = att4 + (size_t)sB * (WW / 4);
            a00_n = __ldcs(apA + ls);  a01_n = __ldcs(apA + ls + 8);
            a10_n = __ldcs(apB + ls);  a11_n = __ldcs(apB + ls + 8);
        }

        // --- sample stream 0 (quad q) ---
        float lowA = floorf(r0_c);
        float alA  = __fsub_rn(r0_c, lowA);
        int ilA = (int)lowA;
        int ihA = ((int)ceilf(r0_c)) & (LWT_ - 1);
        const float4* wlA = (const float4*)(s_wt + ilA * WT_STRIDE);
        const float4* whA = (const float4*)(s_wt + ihA * WT_STRIDE);
        float4 loA0 = wlA[ls], loA1 = wlA[ls + 8];
        float4 hiA0 = whA[ls], hiA1 = whA[ls + 8];

        // --- sample stream 1 (quad q+1) ---
        float lowB = floorf(r1_c);
        float alB  = __fsub_rn(r1_c, lowB);
        int ilB = (int)lowB;
        int ihB = ((int)ceilf(r1_c)) & (LWT_ - 1);
        const float4* wlB = (const float4*)(s_wt + ilB * WT_STRIDE);
        const float4* whB = (const float4*)(s_wt + ihB * WT_STRIDE);
        float4 loB0 = wlB[ls], loB1 = wlB[ls + 8];
        float4 hiB0 = whB[ls], hiB1 = whB[ls + 8];

        float accA;
        accA = a00_c.x * fmaf(alA, hiA0.x - loA0.x, loA0.x);
        accA = fmaf(a00_c.y, fmaf(alA, hiA0.y - loA0.y, loA0.y), accA);
        accA = fmaf(a00_c.z, fmaf(alA, hiA0.z - loA0.z, loA0.z), accA);
        accA = fmaf(a00_c.w, fmaf(alA, hiA0.w - loA0.w, loA0.w), accA);
        accA = fmaf(a01_c.x, fmaf(alA, hiA1.x - loA1.x, loA1.x), accA);
        accA = fmaf(a01_c.y, fmaf(alA, hiA1.y - loA1.y, loA1.y), accA);
        accA = fmaf(a01_c.z, fmaf(alA, hiA1.z - loA1.z, loA1.z), accA);
        accA = fmaf(a01_c.w, fmaf(alA, hiA1.w - loA1.w, loA1.w), accA);

        float accB;
        accB = a10_c.x * fmaf(alB, hiB0.x - loB0.x, loB0.x);
        accB = fmaf(a10_c.y, fmaf(alB, hiB0.y - loB0.y, loB0.y), accB);
        accB = fmaf(a10_c.z, fmaf(alB, hiB0.z - loB0.z, loB0.z), accB);
        accB = fmaf(a10_c.w, fmaf(alB, hiB0.w - loB0.w, loB0.w), accB);
        accB = fmaf(a11_c.x, fmaf(alB, hiB1.x - loB1.x, loB1.x), accB);
        accB = fmaf(a11_c.y, fmaf(alB, hiB1.y - loB1.y, loB1.y), accB);
        accB = fmaf(a11_c.z, fmaf(alB, hiB1.z - loB1.z, loB1.z), accB);
        accB = fmaf(a11_c.w, fmaf(alB, hiB1.w - loB1.w, loB1.w), accB);

        accA += __shfl_xor_sync(0xFFFFFFFFu, accA, 1);
        accB += __shfl_xor_sync(0xFFFFFFFFu, accB, 1);
        accA += __shfl_xor_sync(0xFFFFFFFFu, accA, 2);
        accB += __shfl_xor_sync(0xFFFFFFFFu, accB, 2);
        accA += __shfl_xor_sync(0xFFFFFFFFu, accA, 4);
        accB += __shfl_xor_sync(0xFFFFFFFFu, accB, 4);

        if (ls == 0) {
            out[s0 + 4 * q + grp]       = accA * e0_c;
            out[s0 + 4 * (q + 1) + grp] = accB * e1_c;
        }

        e0_c = e0_n; e1_c = e1_n; r0_c = r0_n; r1_c = r1_n;
        a00_c = a00_n; a01_c = a01_n; a10_c = a10_n; a11_c = a11_n;
    }
}

// ---------------------------------------------------------------------------
extern "C" void kernel_launch(void* const* d_in, const int* in_sizes, int n_in,
                              void* d_out, int out_size) {
    const float* pitch = (const float*)d_in[0];
    const float* env   = (const float*)d_in[1];
    const float* att   = (const float*)d_in[2];
    const float* wt    = (const float*)d_in[3];
    float* out         = (float*)d_out;

    cudaFuncSetAttribute(synth_kernel, cudaFuncAttributeMaxDynamicSharedMemorySize, MAIN_SMEM);

    k1_tilesums<<<(BB * NT1 + 127) / 128, 128>>>(pitch);
    k2_midscan<<<BB, 192>>>();
    synth_kernel<<<148, 1024, MAIN_SMEM>>>(pitch, env, (const float4*)att, wt, out);
}